// round 2
// baseline (speedup 1.0000x reference)
#include <cuda_runtime.h>
#include <cstdint>
#include <climits>
#include <cstddef>

// Problem dims
#define B_ROWS 16384
#define GNN_D  512
#define TR_D   768
#define F_D    1024

// ---------------- device scratch (no allocations allowed) ----------------
__device__ float g_X[(size_t)B_ROWS * 1280];     // [gnn | tr]  (84 MB)
__device__ float g_Y[(size_t)B_ROWS * 2048];     // [P | gelu(h_pre)] (134 MB)
__device__ float g_Wcat[2048 * 1280];            // rows 0..1023 = [Wg|Wt], 1024..2047 = [Cg|Ct]
__device__ float g_Mm[1024 * 1024];              // Wo@Wv
__device__ float g_T1[1024 * 1024];              // W1a@Mm
__device__ float g_T2[1024 * 1024];              // W1b@Mm
__device__ float g_cvec[1024];                   // Wo@bv + bo
__device__ float g_bias1[2048];                  // [bg+bt+b2 | bh]

// ---------------- helpers ----------------
__device__ __forceinline__ float to_tf32(float x) {
    uint32_t u = __float_as_uint(x);
    asm("cvt.rna.tf32.f32 %0, %0;" : "+r"(u));
    return __uint_as_float(u);
}

__device__ __forceinline__ uint32_t tf32u(float x) {
    uint32_t u = __float_as_uint(x);
    asm("cvt.rna.tf32.f32 %0, %0;" : "+r"(u));
    return u;
}

__device__ __forceinline__ float gelu_exact(float x) {
    return 0.5f * x * (1.0f + erff(x * 0.70710678118654752f));
}

__device__ __forceinline__ void mma_tf32_16n8k8(float* c, const uint32_t* a, const uint32_t* b) {
    asm volatile(
        "mma.sync.aligned.m16n8k8.row.col.f32.tf32.tf32.f32 "
        "{%0,%1,%2,%3}, {%4,%5,%6,%7}, {%8,%9}, {%0,%1,%2,%3};\n"
        : "+f"(c[0]), "+f"(c[1]), "+f"(c[2]), "+f"(c[3])
        : "r"(a[0]), "r"(a[1]), "r"(a[2]), "r"(a[3]), "r"(b[0]), "r"(b[1]));
}

__device__ __forceinline__ void cp_async16(float* smem_dst, const float* gsrc) {
    uint32_t s = (uint32_t)__cvta_generic_to_shared(smem_dst);
    asm volatile("cp.async.cg.shared.global [%0], [%1], 16;\n" :: "r"(s), "l"(gsrc));
}
#define CP_ASYNC_COMMIT() asm volatile("cp.async.commit_group;\n" ::: "memory")
#define CP_ASYNC_WAIT0()  asm volatile("cp.async.wait_group 0;\n" ::: "memory")

// ============================================================================
// Pipelined TF32 NT GEMM (double-buffered cp.async):
// C[m][n] = sum_k A[m][k] * Bm[n][k]   (A row-major [M,lda], Bm row-major [N,ldb])
// Epilogue: (+bias[n]) -> (gelu if n >= gelu_from) -> (+Cadd[m][n]).
// Dims exact multiples of tiles (true here).
// ============================================================================
template <int BM, int BN, int BK>
__launch_bounds__(256)
__global__ void gemm_tf32_nt_pipe(const float* __restrict__ A, int lda,
                                  const float* __restrict__ Bm, int ldb,
                                  float* __restrict__ C, int ldc,
                                  int K,
                                  const float* __restrict__ bias,
                                  const float* __restrict__ Cadd, int ldca,
                                  int gelu_from) {
    constexpr int BKP = BK + 4;            // row pitch: 36 floats = 144B (16B aligned)
    constexpr int WM = BM / 2;             // 2 warps along M
    constexpr int WN = BN / 4;             // 4 warps along N
    constexpr int MT = WM / 16;
    constexpr int NT = WN / 8;

    extern __shared__ float smem[];
    float* sA = smem;                      // [2][BM*BKP]
    float* sB = smem + 2 * BM * BKP;       // [2][BN*BKP]

    const int tid  = threadIdx.x;
    const int warp = tid >> 5, lane = tid & 31;
    const int wm = warp >> 2, wn = warp & 3;
    const int r4 = lane >> 2, c4 = lane & 3;
    const int bm = blockIdx.y * BM;
    const int bn = blockIdx.x * BN;

    const float* Ab = A  + (size_t)bm * lda;
    const float* Bb = Bm + (size_t)bn * ldb;

    float acc[MT][NT][4];
#pragma unroll
    for (int mt = 0; mt < MT; mt++)
#pragma unroll
        for (int nt = 0; nt < NT; nt++)
#pragma unroll
            for (int i = 0; i < 4; i++) acc[mt][nt][i] = 0.0f;

    auto load_stage = [&](int kt, int st) {
        float* dA = sA + st * BM * BKP;
        float* dB = sB + st * BN * BKP;
#pragma unroll
        for (int i = 0; i < (BM * BK / 4) / 256; i++) {
            int e = tid + i * 256;
            int row = e / (BK / 4);
            int col = (e % (BK / 4)) * 4;
            cp_async16(dA + row * BKP + col, Ab + (size_t)row * lda + kt + col);
        }
#pragma unroll
        for (int i = 0; i < (BN * BK / 4) / 256; i++) {
            int e = tid + i * 256;
            int row = e / (BK / 4);
            int col = (e % (BK / 4)) * 4;
            cp_async16(dB + row * BKP + col, Bb + (size_t)row * ldb + kt + col);
        }
    };

    // Prologue: fill stage 0
    load_stage(0, 0);
    CP_ASYNC_COMMIT();
    CP_ASYNC_WAIT0();
    __syncthreads();

    int buf = 0;
    for (int kt = 0; kt < K; kt += BK) {
        const bool has_next = (kt + BK) < K;
        if (has_next) {
            load_stage(kt + BK, buf ^ 1);
            CP_ASYNC_COMMIT();
        }

        const float* cA = sA + buf * BM * BKP;
        const float* cB = sB + buf * BN * BKP;
#pragma unroll
        for (int ks = 0; ks < BK; ks += 8) {
            uint32_t af[MT][4];
            uint32_t bf[NT][2];
#pragma unroll
            for (int mt = 0; mt < MT; mt++) {
                const float* p = cA + (wm * WM + mt * 16 + r4) * BKP + ks + c4;
                af[mt][0] = tf32u(p[0]);
                af[mt][1] = tf32u(p[8 * BKP]);
                af[mt][2] = tf32u(p[4]);
                af[mt][3] = tf32u(p[8 * BKP + 4]);
            }
#pragma unroll
            for (int nt = 0; nt < NT; nt++) {
                const float* p = cB + (wn * WN + nt * 8 + r4) * BKP + ks + c4;
                bf[nt][0] = tf32u(p[0]);
                bf[nt][1] = tf32u(p[4]);
            }
#pragma unroll
            for (int mt = 0; mt < MT; mt++)
#pragma unroll
                for (int nt = 0; nt < NT; nt++)
                    mma_tf32_16n8k8(acc[mt][nt], af[mt], bf[nt]);
        }

        if (has_next) CP_ASYNC_WAIT0();
        __syncthreads();
        buf ^= 1;
    }

    // --- epilogue ---
#pragma unroll
    for (int mt = 0; mt < MT; mt++) {
        int gr = bm + wm * WM + mt * 16 + r4;
#pragma unroll
        for (int nt = 0; nt < NT; nt++) {
            int gc = bn + wn * WN + nt * 8 + c4 * 2;
            float2 v0 = make_float2(acc[mt][nt][0], acc[mt][nt][1]);
            float2 v1 = make_float2(acc[mt][nt][2], acc[mt][nt][3]);
            if (bias) {
                float bx = bias[gc], by = bias[gc + 1];
                v0.x += bx; v0.y += by; v1.x += bx; v1.y += by;
            }
            if (gc >= gelu_from) {
                v0.x = gelu_exact(v0.x); v0.y = gelu_exact(v0.y);
                v1.x = gelu_exact(v1.x); v1.y = gelu_exact(v1.y);
            }
            if (Cadd) {
                v0.x += Cadd[(size_t)gr * ldca + gc];
                v0.y += Cadd[(size_t)gr * ldca + gc + 1];
                v1.x += Cadd[(size_t)(gr + 8) * ldca + gc];
                v1.y += Cadd[(size_t)(gr + 8) * ldca + gc + 1];
            }
            *reinterpret_cast<float2*>(C + (size_t)gr * ldc + gc) = v0;
            *reinterpret_cast<float2*>(C + (size_t)(gr + 8) * ldc + gc) = v1;
        }
    }
}

// ============================================================================
// Simple single-buffered TF32 GEMM for the small weight-precompute GEMMs.
// NN: C[m][n] = sum_k A[m][k] * Bm[k][n]
// ============================================================================
template <int BM, int BN, int BK>
__launch_bounds__(256, 2)
__global__ void gemm_tf32_nn(const float* __restrict__ A, int lda,
                             const float* __restrict__ Bm, int ldb,
                             float* __restrict__ C, int ldc, int K) {
    constexpr int BKP = BK + 4;
    constexpr int WM = BM / 2;
    constexpr int WN = BN / 4;
    constexpr int MT = WM / 16;
    constexpr int NT = WN / 8;

    __shared__ float sA[BM * BKP];
    __shared__ float sB[BN * BKP];

    const int tid  = threadIdx.x;
    const int warp = tid >> 5, lane = tid & 31;
    const int wm = warp >> 2, wn = warp & 3;
    const int r4 = lane >> 2, c4 = lane & 3;
    const int bm = blockIdx.y * BM;
    const int bn = blockIdx.x * BN;

    float acc[MT][NT][4];
#pragma unroll
    for (int mt = 0; mt < MT; mt++)
#pragma unroll
        for (int nt = 0; nt < NT; nt++)
#pragma unroll
            for (int i = 0; i < 4; i++) acc[mt][nt][i] = 0.0f;

    const float* Ab = A + (size_t)bm * lda;

    for (int kt = 0; kt < K; kt += BK) {
        {
            constexpr int V = BM * BK / 4;
#pragma unroll
            for (int i = 0; i < V / 256; i++) {
                int e = tid + i * 256;
                int row = e / (BK / 4);
                int col = (e % (BK / 4)) * 4;
                float4 v = *reinterpret_cast<const float4*>(Ab + (size_t)row * lda + kt + col);
                float* d = sA + row * BKP + col;
                d[0] = to_tf32(v.x); d[1] = to_tf32(v.y);
                d[2] = to_tf32(v.z); d[3] = to_tf32(v.w);
            }
        }
        {
            constexpr int E = BN * BK;
#pragma unroll
            for (int i = 0; i < E / 256; i++) {
                int e = tid + i * 256;
                int k = e / BN;
                int n = e % BN;
                sB[n * BKP + k] = to_tf32(Bm[(size_t)(kt + k) * ldb + bn + n]);
            }
        }
        __syncthreads();

#pragma unroll
        for (int ks = 0; ks < BK; ks += 8) {
            uint32_t af[MT][4];
            uint32_t bf[NT][2];
#pragma unroll
            for (int mt = 0; mt < MT; mt++) {
                const float* p = sA + (wm * WM + mt * 16 + r4) * BKP + ks + c4;
                af[mt][0] = __float_as_uint(p[0]);
                af[mt][1] = __float_as_uint(p[8 * BKP]);
                af[mt][2] = __float_as_uint(p[4]);
                af[mt][3] = __float_as_uint(p[8 * BKP + 4]);
            }
#pragma unroll
            for (int nt = 0; nt < NT; nt++) {
                const float* p = sB + (wn * WN + nt * 8 + r4) * BKP + ks + c4;
                bf[nt][0] = __float_as_uint(p[0]);
                bf[nt][1] = __float_as_uint(p[4]);
            }
#pragma unroll
            for (int mt = 0; mt < MT; mt++)
#pragma unroll
                for (int nt = 0; nt < NT; nt++)
                    mma_tf32_16n8k8(acc[mt][nt], af[mt], bf[nt]);
        }
        __syncthreads();
    }

#pragma unroll
    for (int mt = 0; mt < MT; mt++) {
        int gr = bm + wm * WM + mt * 16 + r4;
#pragma unroll
        for (int nt = 0; nt < NT; nt++) {
            int gc = bn + wn * WN + nt * 8 + c4 * 2;
            float2 v0 = make_float2(acc[mt][nt][0], acc[mt][nt][1]);
            float2 v1 = make_float2(acc[mt][nt][2], acc[mt][nt][3]);
            *reinterpret_cast<float2*>(C + (size_t)gr * ldc + gc) = v0;
            *reinterpret_cast<float2*>(C + (size_t)(gr + 8) * ldc + gc) = v1;
        }
    }
}

// ---------------- pack kernels ----------------
__global__ void pack_X_kernel(const float* __restrict__ gnn, const float* __restrict__ tr,
                              float* __restrict__ X) {
    const int R4 = 1280 / 4;  // 320
    size_t i = (size_t)blockIdx.x * blockDim.x + threadIdx.x;
    if (i >= (size_t)B_ROWS * R4) return;
    int row = (int)(i / R4);
    int c4  = (int)(i % R4);
    float4 v;
    if (c4 < GNN_D / 4)
        v = reinterpret_cast<const float4*>(gnn)[(size_t)row * (GNN_D / 4) + c4];
    else
        v = reinterpret_cast<const float4*>(tr)[(size_t)row * (TR_D / 4) + (c4 - GNN_D / 4)];
    reinterpret_cast<float4*>(X)[i] = v;
}

__global__ void pack_W_kernel(const float* __restrict__ Wg, const float* __restrict__ Wt,
                              float* __restrict__ Wcat) {
    const int R4 = 1280 / 4;
    size_t i = (size_t)blockIdx.x * blockDim.x + threadIdx.x;
    if (i >= (size_t)F_D * R4) return;
    int row = (int)(i / R4);
    int c4  = (int)(i % R4);
    float4 v;
    if (c4 < GNN_D / 4)
        v = reinterpret_cast<const float4*>(Wg)[(size_t)row * (GNN_D / 4) + c4];
    else
        v = reinterpret_cast<const float4*>(Wt)[(size_t)row * (TR_D / 4) + (c4 - GNN_D / 4)];
    reinterpret_cast<float4*>(Wcat)[i] = v;
}

// ---------------- bias kernels (tiny) ----------------
__global__ void bias_c_kernel(const float* __restrict__ Wo, const float* __restrict__ bv,
                              const float* __restrict__ bo, float* __restrict__ cvec) {
    int i = blockIdx.x * blockDim.x + threadIdx.x;
    if (i >= F_D) return;
    float s = bo[i];
    const float* r = Wo + (size_t)i * F_D;
    for (int k = 0; k < F_D; k++) s += r[k] * bv[k];
    cvec[i] = s;
}

// bias1[0:1024]    = bg + bt + b2
// bias1[1024:2048] = b1 + T1@bt + T2@bg + (W1a + W1b)@cvec
__global__ void bias_rest_kernel(const float* __restrict__ T1, const float* __restrict__ T2,
                                 const float* __restrict__ W1, const float* __restrict__ b1,
                                 const float* __restrict__ bg, const float* __restrict__ bt,
                                 const float* __restrict__ b2, const float* __restrict__ cvec,
                                 float* __restrict__ bias1) {
    int i = blockIdx.x * blockDim.x + threadIdx.x;
    if (i >= F_D) return;
    float s = b1[i];
    const float* r1 = T1 + (size_t)i * F_D;
    const float* r2 = T2 + (size_t)i * F_D;
    const float* w1 = W1 + (size_t)i * (2 * F_D);
    for (int k = 0; k < F_D; k++) {
        s += r1[k] * bt[k];
        s += r2[k] * bg[k];
        s += (w1[k] + w1[F_D + k]) * cvec[k];
    }
    bias1[F_D + i] = s;
    bias1[i] = bg[i] + bt[i] + b2[i];
}

// ---------------- host-side launch helpers ----------------
static void run_gemm128nt(const float* A, int lda, const float* Bm, int ldb,
                          float* C, int ldc, int M, int N, int K,
                          const float* bias, const float* Cadd, int ldca, int gelu_from) {
    constexpr int BM = 128, BN = 128, BK = 32;
    constexpr int SMEM = 2 * (BM + BN) * (BK + 4) * (int)sizeof(float);  // 73728 B
    cudaFuncSetAttribute(gemm_tf32_nt_pipe<BM, BN, BK>,
                         cudaFuncAttributeMaxDynamicSharedMemorySize, SMEM);
    dim3 grid(N / BN, M / BM);
    gemm_tf32_nt_pipe<BM, BN, BK><<<grid, 256, SMEM>>>(A, lda, Bm, ldb, C, ldc, K,
                                                       bias, Cadd, ldca, gelu_from);
}

static void run_gemm64nn(const float* A, int lda, const float* Bm, int ldb,
                         float* C, int ldc, int M, int N, int K) {
    dim3 grid(N / 64, M / 64);
    gemm_tf32_nn<64, 64, 32><<<grid, 256>>>(A, lda, Bm, ldb, C, ldc, K);
}

extern "C" void kernel_launch(void* const* d_in, const int* in_sizes, int n_in,
                              void* d_out, int out_size) {
    const float* gnn = (const float*)d_in[0];
    const float* tr  = (const float*)d_in[1];
    const float* Wg  = (const float*)d_in[2];
    const float* bg  = (const float*)d_in[3];
    const float* Wt  = (const float*)d_in[4];
    const float* bt  = (const float*)d_in[5];
    const float* Wv  = (const float*)d_in[6];
    const float* bv  = (const float*)d_in[7];
    const float* Wo  = (const float*)d_in[8];
    const float* bo  = (const float*)d_in[9];
    const float* W1  = (const float*)d_in[10];
    const float* b1  = (const float*)d_in[11];
    const float* W2  = (const float*)d_in[12];
    const float* b2  = (const float*)d_in[13];
    float* out = (float*)d_out;

    float *X, *Y, *Wcat, *Mm, *T1, *T2, *cvec, *bias1;
    cudaGetSymbolAddress((void**)&X,     g_X);
    cudaGetSymbolAddress((void**)&Y,     g_Y);
    cudaGetSymbolAddress((void**)&Wcat,  g_Wcat);
    cudaGetSymbolAddress((void**)&Mm,    g_Mm);
    cudaGetSymbolAddress((void**)&T1,    g_T1);
    cudaGetSymbolAddress((void**)&T2,    g_T2);
    cudaGetSymbolAddress((void**)&cvec,  g_cvec);
    cudaGetSymbolAddress((void**)&bias1, g_bias1);

    // Pack activations X = [gnn | tr] and projection weights Wcat[0:1024] = [Wg | Wt]
    {
        size_t n4 = (size_t)B_ROWS * (1280 / 4);
        pack_X_kernel<<<(unsigned)((n4 + 255) / 256), 256>>>(gnn, tr, X);
        size_t w4 = (size_t)F_D * (1280 / 4);
        pack_W_kernel<<<(unsigned)((w4 + 255) / 256), 256>>>(Wg, Wt, Wcat);
    }

    // Weight-space precompute (collapse attention + fusion layer 1):
    // Mm = Wo @ Wv;  T1 = W1a @ Mm;  T2 = W1b @ Mm;
    // Wcat[1024:2048] = [Cg | Ct] = [T2@Wg | T1@Wt]
    run_gemm64nn(Wo, F_D, Wv, F_D, Mm, F_D, F_D, F_D, F_D);
    run_gemm64nn(W1, 2 * F_D, Mm, F_D, T1, F_D, F_D, F_D, F_D);
    run_gemm64nn(W1 + F_D, 2 * F_D, Mm, F_D, T2, F_D, F_D, F_D, F_D);
    run_gemm64nn(T2, F_D, Wg, GNN_D, Wcat + (size_t)F_D * 1280, 1280, F_D, GNN_D, F_D);
    run_gemm64nn(T1, F_D, Wt, TR_D, Wcat + (size_t)F_D * 1280 + GNN_D, 1280, F_D, TR_D, F_D);

    // Bias vectors
    bias_c_kernel<<<8, 128>>>(Wo, bv, bo, cvec);
    bias_rest_kernel<<<8, 128>>>(T1, T2, W1, b1, bg, bt, b2, cvec, bias1);

    // GEMM1: Y[:, 0:1024]   = X @ [Wg|Wt].T + (bg+bt+b2)           (= P, with b2 folded in)
    //        Y[:, 1024:2048]= gelu(X @ [Cg|Ct].T + bh)             (gelu fused in epilogue)
    run_gemm128nt(X, 1280, Wcat, 1280, Y, 2048, B_ROWS, 2048, 1280, bias1, nullptr, 0, 1024);

    // GEMM2: out = gelu(h_pre) @ W2.T + P
    run_gemm128nt(Y + F_D, 2048, W2, F_D, out, F_D, B_ROWS, F_D, F_D, nullptr, Y, 2048, INT_MAX);
}

// round 3
// speedup vs baseline: 1.0902x; 1.0902x over previous
#include <cuda_runtime.h>
#include <cstdint>
#include <climits>
#include <cstddef>

// Problem dims
#define B_ROWS 16384
#define GNN_D  512
#define TR_D   768
#define F_D    1024

// ---------------- device scratch (no allocations allowed) ----------------
__device__ float g_X[(size_t)B_ROWS * 1280];     // [gnn | tr] tf32-rounded (84 MB)
__device__ float g_Y[(size_t)B_ROWS * 2048];     // [P | gelu(h_pre)] (134 MB)
__device__ float g_Wcat[2048 * 1280];            // rows 0..1023 = [Wg|Wt], 1024..2047 = [Cg|Ct]
__device__ float g_Mm[1024 * 1024];              // Wo@Wv
__device__ float g_W1s[2048 * 1024];             // [W1a ; W1b] stacked
__device__ float g_Tcat[2048 * 1024];            // [T1 ; T2]
__device__ float g_W2r[1024 * 1024];             // W2 tf32-rounded
__device__ float g_cvec[1024];                   // Wo@bv + bo
__device__ float g_bias1[2048];                  // [bg+bt+b2 | bh]

// ---------------- helpers ----------------
__device__ __forceinline__ float to_tf32(float x) {
    uint32_t u = __float_as_uint(x);
    asm("cvt.rna.tf32.f32 %0, %0;" : "+r"(u));
    return __uint_as_float(u);
}

__device__ __forceinline__ float gelu_exact(float x) {
    return 0.5f * x * (1.0f + erff(x * 0.70710678118654752f));
}

__device__ __forceinline__ void mma_tf32_16n8k8(float* c, const uint32_t* a, const uint32_t* b) {
    asm volatile(
        "mma.sync.aligned.m16n8k8.row.col.f32.tf32.tf32.f32 "
        "{%0,%1,%2,%3}, {%4,%5,%6,%7}, {%8,%9}, {%0,%1,%2,%3};\n"
        : "+f"(c[0]), "+f"(c[1]), "+f"(c[2]), "+f"(c[3])
        : "r"(a[0]), "r"(a[1]), "r"(a[2]), "r"(a[3]), "r"(b[0]), "r"(b[1]));
}

__device__ __forceinline__ void cp_async16(float* smem_dst, const float* gsrc) {
    uint32_t s = (uint32_t)__cvta_generic_to_shared(smem_dst);
    asm volatile("cp.async.cg.shared.global [%0], [%1], 16;\n" :: "r"(s), "l"(gsrc));
}
#define CP_ASYNC_COMMIT() asm volatile("cp.async.commit_group;\n" ::: "memory")
#define CP_ASYNC_WAIT0()  asm volatile("cp.async.wait_group 0;\n" ::: "memory")

// ============================================================================
// Big NT GEMM: 128x128 block, 4 warps (2x2), 64x64 warp tile, cp.async 2-stage.
// C[m][n] = sum_k A[m][k] * Bm[n][k]. A,Bm assumed tf32-prerounded.
// Epilogue: (+bias[n]) -> (gelu + tf32 round if n >= gelu_from) -> (+Cadd[m][n]).
// ============================================================================
template <int BM, int BN, int BK>
__launch_bounds__(128, 2)
__global__ void gemm_tf32_nt_big(const float* __restrict__ A, int lda,
                                 const float* __restrict__ Bm, int ldb,
                                 float* __restrict__ C, int ldc,
                                 int K,
                                 const float* __restrict__ bias,
                                 const float* __restrict__ Cadd, int ldca,
                                 int gelu_from) {
    constexpr int BKP = BK + 4;      // 36-float pitch, conflict-free fragment loads
    constexpr int WM = 64, WN = 64;
    constexpr int MT = WM / 16;      // 4
    constexpr int NT = WN / 8;       // 8

    extern __shared__ float smem[];
    float* sA = smem;                      // [2][BM*BKP]
    float* sB = smem + 2 * BM * BKP;       // [2][BN*BKP]

    const int tid  = threadIdx.x;
    const int warp = tid >> 5, lane = tid & 31;
    const int wm = warp >> 1, wn = warp & 1;
    const int r4 = lane >> 2, c4 = lane & 3;
    const int bm = blockIdx.y * BM;
    const int bn = blockIdx.x * BN;

    const float* Ab = A  + (size_t)bm * lda;
    const float* Bb = Bm + (size_t)bn * ldb;

    float acc[MT][NT][4];
#pragma unroll
    for (int mt = 0; mt < MT; mt++)
#pragma unroll
        for (int nt = 0; nt < NT; nt++)
#pragma unroll
            for (int i = 0; i < 4; i++) acc[mt][nt][i] = 0.0f;

    auto load_stage = [&](int kt, int st) {
        float* dA = sA + st * BM * BKP;
        float* dB = sB + st * BN * BKP;
#pragma unroll
        for (int i = 0; i < (BM * BK / 4) / 128; i++) {
            int e = tid + i * 128;
            int row = e / (BK / 4);
            int col = (e % (BK / 4)) * 4;
            cp_async16(dA + row * BKP + col, Ab + (size_t)row * lda + kt + col);
        }
#pragma unroll
        for (int i = 0; i < (BN * BK / 4) / 128; i++) {
            int e = tid + i * 128;
            int row = e / (BK / 4);
            int col = (e % (BK / 4)) * 4;
            cp_async16(dB + row * BKP + col, Bb + (size_t)row * ldb + kt + col);
        }
    };

    load_stage(0, 0);
    CP_ASYNC_COMMIT();
    CP_ASYNC_WAIT0();
    __syncthreads();

    int buf = 0;
    for (int kt = 0; kt < K; kt += BK) {
        const bool has_next = (kt + BK) < K;
        if (has_next) {
            load_stage(kt + BK, buf ^ 1);
            CP_ASYNC_COMMIT();
        }

        const float* cA = sA + buf * BM * BKP;
        const float* cB = sB + buf * BN * BKP;
#pragma unroll
        for (int ks = 0; ks < BK; ks += 8) {
            uint32_t af[MT][4];
            uint32_t bf[NT][2];
#pragma unroll
            for (int mt = 0; mt < MT; mt++) {
                const float* p = cA + (wm * WM + mt * 16 + r4) * BKP + ks + c4;
                af[mt][0] = __float_as_uint(p[0]);
                af[mt][1] = __float_as_uint(p[8 * BKP]);
                af[mt][2] = __float_as_uint(p[4]);
                af[mt][3] = __float_as_uint(p[8 * BKP + 4]);
            }
#pragma unroll
            for (int nt = 0; nt < NT; nt++) {
                const float* p = cB + (wn * WN + nt * 8 + r4) * BKP + ks + c4;
                bf[nt][0] = __float_as_uint(p[0]);
                bf[nt][1] = __float_as_uint(p[4]);
            }
#pragma unroll
            for (int mt = 0; mt < MT; mt++)
#pragma unroll
                for (int nt = 0; nt < NT; nt++)
                    mma_tf32_16n8k8(acc[mt][nt], af[mt], bf[nt]);
        }

        if (has_next) CP_ASYNC_WAIT0();
        __syncthreads();
        buf ^= 1;
    }

    // --- epilogue ---
#pragma unroll
    for (int mt = 0; mt < MT; mt++) {
        int gr = bm + wm * WM + mt * 16 + r4;
#pragma unroll
        for (int nt = 0; nt < NT; nt++) {
            int gc = bn + wn * WN + nt * 8 + c4 * 2;
            float2 v0 = make_float2(acc[mt][nt][0], acc[mt][nt][1]);
            float2 v1 = make_float2(acc[mt][nt][2], acc[mt][nt][3]);
            if (bias) {
                float bx = bias[gc], by = bias[gc + 1];
                v0.x += bx; v0.y += by; v1.x += bx; v1.y += by;
            }
            if (gc >= gelu_from) {
                // gelu + tf32 pre-round (this output feeds GEMM2's A operand)
                v0.x = to_tf32(gelu_exact(v0.x)); v0.y = to_tf32(gelu_exact(v0.y));
                v1.x = to_tf32(gelu_exact(v1.x)); v1.y = to_tf32(gelu_exact(v1.y));
            }
            if (Cadd) {
                v0.x += Cadd[(size_t)gr * ldca + gc];
                v0.y += Cadd[(size_t)gr * ldca + gc + 1];
                v1.x += Cadd[(size_t)(gr + 8) * ldca + gc];
                v1.y += Cadd[(size_t)(gr + 8) * ldca + gc + 1];
            }
            *reinterpret_cast<float2*>(C + (size_t)gr * ldc + gc) = v0;
            *reinterpret_cast<float2*>(C + (size_t)(gr + 8) * ldc + gc) = v1;
        }
    }
}

// ============================================================================
// Pipelined NN GEMM for weight precompute: 128x128 block, 256 thr (2x4 warps,
// 64x32 warp tiles), cp.async 2-stage. C = A[M,K] @ Bm[K,N].
// Epilogue rounds result to tf32 (outputs feed later GEMMs as operands).
// ============================================================================
template <int BM, int BN, int BK>
__launch_bounds__(256)
__global__ void gemm_tf32_nn_pipe(const float* __restrict__ A, int lda,
                                  const float* __restrict__ Bm, int ldb,
                                  float* __restrict__ C, int ldc, int K) {
    constexpr int BKP = BK + 4;
    constexpr int BNP = BN + 4;
    constexpr int WM = BM / 2;       // 64
    constexpr int WN = BN / 4;       // 32
    constexpr int MT = WM / 16;      // 4
    constexpr int NT = WN / 8;       // 4

    extern __shared__ float smem[];
    float* sA = smem;                      // [2][BM*BKP]
    float* sB = smem + 2 * BM * BKP;       // [2][BK*BNP]  (k-major)

    const int tid  = threadIdx.x;
    const int warp = tid >> 5, lane = tid & 31;
    const int wm = warp >> 2, wn = warp & 3;
    const int r4 = lane >> 2, c4 = lane & 3;
    const int bm = blockIdx.y * BM;
    const int bn = blockIdx.x * BN;

    const float* Ab = A + (size_t)bm * lda;

    float acc[MT][NT][4];
#pragma unroll
    for (int mt = 0; mt < MT; mt++)
#pragma unroll
        for (int nt = 0; nt < NT; nt++)
#pragma unroll
            for (int i = 0; i < 4; i++) acc[mt][nt][i] = 0.0f;

    auto load_stage = [&](int kt, int st) {
        float* dA = sA + st * BM * BKP;
        float* dB = sB + st * BK * BNP;
#pragma unroll
        for (int i = 0; i < (BM * BK / 4) / 256; i++) {
            int e = tid + i * 256;
            int row = e / (BK / 4);
            int col = (e % (BK / 4)) * 4;
            cp_async16(dA + row * BKP + col, Ab + (size_t)row * lda + kt + col);
        }
#pragma unroll
        for (int i = 0; i < (BK * BN / 4) / 256; i++) {
            int e = tid + i * 256;
            int row = e / (BN / 4);              // k index
            int col = (e % (BN / 4)) * 4;        // n index
            cp_async16(dB + row * BNP + col, Bm + (size_t)(kt + row) * ldb + bn + col);
        }
    };

    load_stage(0, 0);
    CP_ASYNC_COMMIT();
    CP_ASYNC_WAIT0();
    __syncthreads();

    int buf = 0;
    for (int kt = 0; kt < K; kt += BK) {
        const bool has_next = (kt + BK) < K;
        if (has_next) {
            load_stage(kt + BK, buf ^ 1);
            CP_ASYNC_COMMIT();
        }

        const float* cA = sA + buf * BM * BKP;
        const float* cB = sB + buf * BK * BNP;
#pragma unroll
        for (int ks = 0; ks < BK; ks += 8) {
            uint32_t af[MT][4];
            uint32_t bf[NT][2];
#pragma unroll
            for (int mt = 0; mt < MT; mt++) {
                const float* p = cA + (wm * WM + mt * 16 + r4) * BKP + ks + c4;
                // raw fp32 -> tf32 semantics: mma truncates; inputs here are
                // either raw weights (ok: ~2^-12 effect) or tf32-rounded.
                af[mt][0] = __float_as_uint(p[0]);
                af[mt][1] = __float_as_uint(p[8 * BKP]);
                af[mt][2] = __float_as_uint(p[4]);
                af[mt][3] = __float_as_uint(p[8 * BKP + 4]);
            }
#pragma unroll
            for (int nt = 0; nt < NT; nt++) {
                const float* p = cB + (size_t)(ks + c4) * BNP + wn * WN + nt * 8 + r4;
                bf[nt][0] = __float_as_uint(p[0]);
                bf[nt][1] = __float_as_uint(p[4 * BNP]);
            }
#pragma unroll
            for (int mt = 0; mt < MT; mt++)
#pragma unroll
                for (int nt = 0; nt < NT; nt++)
                    mma_tf32_16n8k8(acc[mt][nt], af[mt], bf[nt]);
        }

        if (has_next) CP_ASYNC_WAIT0();
        __syncthreads();
        buf ^= 1;
    }

#pragma unroll
    for (int mt = 0; mt < MT; mt++) {
        int gr = bm + wm * WM + mt * 16 + r4;
#pragma unroll
        for (int nt = 0; nt < NT; nt++) {
            int gc = bn + wn * WN + nt * 8 + c4 * 2;
            float2 v0 = make_float2(to_tf32(acc[mt][nt][0]), to_tf32(acc[mt][nt][1]));
            float2 v1 = make_float2(to_tf32(acc[mt][nt][2]), to_tf32(acc[mt][nt][3]));
            *reinterpret_cast<float2*>(C + (size_t)gr * ldc + gc) = v0;
            *reinterpret_cast<float2*>(C + (size_t)(gr + 8) * ldc + gc) = v1;
        }
    }
}

// ---------------- pack kernels (tf32 pre-round) ----------------
__global__ void pack_X_kernel(const float* __restrict__ gnn, const float* __restrict__ tr,
                              float* __restrict__ X) {
    const int R4 = 1280 / 4;
    size_t i = (size_t)blockIdx.x * blockDim.x + threadIdx.x;
    if (i >= (size_t)B_ROWS * R4) return;
    int row = (int)(i / R4);
    int c4  = (int)(i % R4);
    float4 v;
    if (c4 < GNN_D / 4)
        v = reinterpret_cast<const float4*>(gnn)[(size_t)row * (GNN_D / 4) + c4];
    else
        v = reinterpret_cast<const float4*>(tr)[(size_t)row * (TR_D / 4) + (c4 - GNN_D / 4)];
    v.x = to_tf32(v.x); v.y = to_tf32(v.y); v.z = to_tf32(v.z); v.w = to_tf32(v.w);
    reinterpret_cast<float4*>(X)[i] = v;
}

__global__ void pack_W_kernel(const float* __restrict__ Wg, const float* __restrict__ Wt,
                              float* __restrict__ Wcat) {
    const int R4 = 1280 / 4;
    size_t i = (size_t)blockIdx.x * blockDim.x + threadIdx.x;
    if (i >= (size_t)F_D * R4) return;
    int row = (int)(i / R4);
    int c4  = (int)(i % R4);
    float4 v;
    if (c4 < GNN_D / 4)
        v = reinterpret_cast<const float4*>(Wg)[(size_t)row * (GNN_D / 4) + c4];
    else
        v = reinterpret_cast<const float4*>(Wt)[(size_t)row * (TR_D / 4) + (c4 - GNN_D / 4)];
    v.x = to_tf32(v.x); v.y = to_tf32(v.y); v.z = to_tf32(v.z); v.w = to_tf32(v.w);
    reinterpret_cast<float4*>(Wcat)[i] = v;
}

// W1s = [W1[:, :1024] ; W1[:, 1024:]]  (stacked rows, 2048x1024)
__global__ void pack_W1s_kernel(const float* __restrict__ W1, float* __restrict__ W1s) {
    const int R4 = F_D / 4;  // 256
    size_t i = (size_t)blockIdx.x * blockDim.x + threadIdx.x;
    if (i >= (size_t)2 * F_D * R4) return;
    int row = (int)(i / R4);           // 0..2047
    int c4  = (int)(i % R4);
    int srow = row & (F_D - 1);
    int half = row >> 10;              // 0: W1a, 1: W1b
    float4 v = reinterpret_cast<const float4*>(W1)[(size_t)srow * (2 * F_D / 4) + half * R4 + c4];
    reinterpret_cast<float4*>(W1s)[i] = v;
}

// W2r = tf32_round(W2)
__global__ void round_W2_kernel(const float* __restrict__ W2, float* __restrict__ W2r) {
    size_t i = (size_t)blockIdx.x * blockDim.x + threadIdx.x;
    if (i >= (size_t)F_D * F_D / 4) return;
    float4 v = reinterpret_cast<const float4*>(W2)[i];
    v.x = to_tf32(v.x); v.y = to_tf32(v.y); v.z = to_tf32(v.z); v.w = to_tf32(v.w);
    reinterpret_cast<float4*>(W2r)[i] = v;
}

// ---------------- bias kernels (tiny, fp32) ----------------
__global__ void bias_c_kernel(const float* __restrict__ Wo, const float* __restrict__ bv,
                              const float* __restrict__ bo, float* __restrict__ cvec) {
    int i = blockIdx.x * blockDim.x + threadIdx.x;
    if (i >= F_D) return;
    float s = bo[i];
    const float* r = Wo + (size_t)i * F_D;
    for (int k = 0; k < F_D; k++) s += r[k] * bv[k];
    cvec[i] = s;
}

// bias1[0:1024]    = bg + bt + b2
// bias1[1024:2048] = b1 + T1@bt + T2@bg + (W1a + W1b)@cvec
__global__ void bias_rest_kernel(const float* __restrict__ Tcat,
                                 const float* __restrict__ W1, const float* __restrict__ b1,
                                 const float* __restrict__ bg, const float* __restrict__ bt,
                                 const float* __restrict__ b2, const float* __restrict__ cvec,
                                 float* __restrict__ bias1) {
    int i = blockIdx.x * blockDim.x + threadIdx.x;
    if (i >= F_D) return;
    float s = b1[i];
    const float* r1 = Tcat + (size_t)i * F_D;                       // T1 row i
    const float* r2 = Tcat + (size_t)(F_D + i) * F_D;               // T2 row i
    const float* w1 = W1 + (size_t)i * (2 * F_D);
    for (int k = 0; k < F_D; k++) {
        s += r1[k] * bt[k];
        s += r2[k] * bg[k];
        s += (w1[k] + w1[F_D + k]) * cvec[k];
    }
    bias1[F_D + i] = s;
    bias1[i] = bg[i] + bt[i] + b2[i];
}

// ---------------- host-side launch helpers ----------------
static void run_gemm_nt(const float* A, int lda, const float* Bm, int ldb,
                        float* C, int ldc, int M, int N, int K,
                        const float* bias, const float* Cadd, int ldca, int gelu_from) {
    constexpr int BM = 128, BN = 128, BK = 32;
    constexpr int SMEM = 2 * (BM + BN) * (BK + 4) * (int)sizeof(float);  // 73728 B
    static bool attr_done = false;
    if (!attr_done) {
        cudaFuncSetAttribute(gemm_tf32_nt_big<BM, BN, BK>,
                             cudaFuncAttributeMaxDynamicSharedMemorySize, SMEM);
        attr_done = true;
    }
    dim3 grid(N / BN, M / BM);
    gemm_tf32_nt_big<BM, BN, BK><<<grid, 128, SMEM>>>(A, lda, Bm, ldb, C, ldc, K,
                                                      bias, Cadd, ldca, gelu_from);
}

static void run_gemm_nn(const float* A, int lda, const float* Bm, int ldb,
                        float* C, int ldc, int M, int N, int K) {
    constexpr int BM = 128, BN = 128, BK = 32;
    constexpr int SMEM = (2 * BM * (BK + 4) + 2 * BK * (BN + 4)) * (int)sizeof(float); // 70656 B
    static bool attr_done = false;
    if (!attr_done) {
        cudaFuncSetAttribute(gemm_tf32_nn_pipe<BM, BN, BK>,
                             cudaFuncAttributeMaxDynamicSharedMemorySize, SMEM);
        attr_done = true;
    }
    dim3 grid(N / BN, M / BM);
    gemm_tf32_nn_pipe<BM, BN, BK><<<grid, 256, SMEM>>>(A, lda, Bm, ldb, C, ldc, K);
}

extern "C" void kernel_launch(void* const* d_in, const int* in_sizes, int n_in,
                              void* d_out, int out_size) {
    const float* gnn = (const float*)d_in[0];
    const float* tr  = (const float*)d_in[1];
    const float* Wg  = (const float*)d_in[2];
    const float* bg  = (const float*)d_in[3];
    const float* Wt  = (const float*)d_in[4];
    const float* bt  = (const float*)d_in[5];
    const float* Wv  = (const float*)d_in[6];
    const float* bv  = (const float*)d_in[7];
    const float* Wo  = (const float*)d_in[8];
    const float* bo  = (const float*)d_in[9];
    const float* W1  = (const float*)d_in[10];
    const float* b1  = (const float*)d_in[11];
    const float* W2  = (const float*)d_in[12];
    const float* b2  = (const float*)d_in[13];
    float* out = (float*)d_out;

    float *X, *Y, *Wcat, *Mm, *W1s, *Tcat, *W2r, *cvec, *bias1;
    cudaGetSymbolAddress((void**)&X,     g_X);
    cudaGetSymbolAddress((void**)&Y,     g_Y);
    cudaGetSymbolAddress((void**)&Wcat,  g_Wcat);
    cudaGetSymbolAddress((void**)&Mm,    g_Mm);
    cudaGetSymbolAddress((void**)&W1s,   g_W1s);
    cudaGetSymbolAddress((void**)&Tcat,  g_Tcat);
    cudaGetSymbolAddress((void**)&W2r,   g_W2r);
    cudaGetSymbolAddress((void**)&cvec,  g_cvec);
    cudaGetSymbolAddress((void**)&bias1, g_bias1);

    // Packs (tf32 pre-round where values feed mma A/B operands)
    {
        size_t n4 = (size_t)B_ROWS * (1280 / 4);
        pack_X_kernel<<<(unsigned)((n4 + 255) / 256), 256>>>(gnn, tr, X);
        size_t w4 = (size_t)F_D * (1280 / 4);
        pack_W_kernel<<<(unsigned)((w4 + 255) / 256), 256>>>(Wg, Wt, Wcat);
        size_t s4 = (size_t)2 * F_D * (F_D / 4);
        pack_W1s_kernel<<<(unsigned)((s4 + 255) / 256), 256>>>(W1, W1s);
        size_t r4 = (size_t)F_D * F_D / 4;
        round_W2_kernel<<<(unsigned)((r4 + 255) / 256), 256>>>(W2, W2r);
    }

    // Weight-space precompute:
    // Mm = Wo@Wv;  [T1;T2] = W1s@Mm;  Wcat[1024:2048] = [T2@Wg | T1@Wt]
    run_gemm_nn(Wo, F_D, Wv, F_D, Mm, F_D, F_D, F_D, F_D);
    run_gemm_nn(W1s, F_D, Mm, F_D, Tcat, F_D, 2 * F_D, F_D, F_D);
    run_gemm_nn(Tcat + (size_t)F_D * F_D, F_D, Wg, GNN_D,
                Wcat + (size_t)F_D * 1280, 1280, F_D, GNN_D, F_D);           // Cg = T2@Wg
    run_gemm_nn(Tcat, F_D, Wt, TR_D,
                Wcat + (size_t)F_D * 1280 + GNN_D, 1280, F_D, TR_D, F_D);    // Ct = T1@Wt

    // Bias vectors
    bias_c_kernel<<<8, 128>>>(Wo, bv, bo, cvec);
    bias_rest_kernel<<<8, 128>>>(Tcat, W1, b1, bg, bt, b2, cvec, bias1);

    // GEMM1: Y[:, 0:1024]    = X @ [Wg|Wt].T + (bg+bt+b2)     (= P)
    //        Y[:, 1024:2048] = tf32(gelu(X @ [Cg|Ct].T + bh))
    run_gemm_nt(X, 1280, Wcat, 1280, Y, 2048, B_ROWS, 2048, 1280, bias1, nullptr, 0, 1024);

    // GEMM2: out = gelu(h_pre) @ W2.T + P
    run_gemm_nt(Y + F_D, 2048, W2r, F_D, out, F_D, B_ROWS, F_D, F_D, nullptr, Y, 2048, INT_MAX);
}

// round 17
// speedup vs baseline: 1.5203x; 1.3944x over previous
#include <cuda_runtime.h>
#include <cuda_fp16.h>
#include <cstdint>
#include <climits>
#include <cstddef>

// Problem dims
#define B_ROWS 16384
#define GNN_D  512
#define TR_D   768
#define F_D    1024

// ---------------- device scratch (no allocations allowed) ----------------
__device__ __half g_Xh[(size_t)B_ROWS * 1280];   // [gnn | tr] fp16 (42 MB)
__device__ __half g_H[(size_t)B_ROWS * 1024];    // gelu(h_pre) fp16 (33.5 MB)
__device__ float  g_P[(size_t)B_ROWS * 1024];    // P = X@[Wg|Wt].T + bias, fp32 (67 MB)
__device__ float  g_Wcat[2048 * 1280];           // fp32: rows 0..1023=[Wg|Wt], 1024..2047=[Cg|Ct]
__device__ __half g_Wh[2048 * 1280];             // fp16 copy of Wcat
__device__ __half g_W2h[1024 * 1024];            // W2 fp16
__device__ float  g_Mm[1024 * 1024];             // Wo@Wv
__device__ float  g_W1s[2048 * 1024];            // [W1a ; W1b] stacked
__device__ float  g_Tcat[2048 * 1024];           // [T1 ; T2]
__device__ float  g_cvec[1024];                  // Wo@bv + bo
__device__ float  g_bias1[2048];                 // [bg+bt+b2 | bh]

// ---------------- helpers ----------------
__device__ __forceinline__ float to_tf32(float x) {
    uint32_t u = __float_as_uint(x);
    asm("cvt.rna.tf32.f32 %0, %0;" : "+r"(u));
    return __uint_as_float(u);
}

__device__ __forceinline__ float gelu_exact(float x) {
    return 0.5f * x * (1.0f + erff(x * 0.70710678118654752f));
}

__device__ __forceinline__ void mma_tf32_16n8k8(float* c, const uint32_t* a, const uint32_t* b) {
    asm volatile(
        "mma.sync.aligned.m16n8k8.row.col.f32.tf32.tf32.f32 "
        "{%0,%1,%2,%3}, {%4,%5,%6,%7}, {%8,%9}, {%0,%1,%2,%3};\n"
        : "+f"(c[0]), "+f"(c[1]), "+f"(c[2]), "+f"(c[3])
        : "r"(a[0]), "r"(a[1]), "r"(a[2]), "r"(a[3]), "r"(b[0]), "r"(b[1]));
}

__device__ __forceinline__ void mma_f16_16n8k16(float* c, const uint32_t* a, const uint32_t* b) {
    asm volatile(
        "mma.sync.aligned.m16n8k16.row.col.f32.f16.f16.f32 "
        "{%0,%1,%2,%3}, {%4,%5,%6,%7}, {%8,%9}, {%0,%1,%2,%3};\n"
        : "+f"(c[0]), "+f"(c[1]), "+f"(c[2]), "+f"(c[3])
        : "r"(a[0]), "r"(a[1]), "r"(a[2]), "r"(a[3]), "r"(b[0]), "r"(b[1]));
}

__device__ __forceinline__ void cp_async16(void* smem_dst, const void* gsrc) {
    uint32_t s = (uint32_t)__cvta_generic_to_shared(smem_dst);
    asm volatile("cp.async.cg.shared.global [%0], [%1], 16;\n" :: "r"(s), "l"(gsrc));
}
#define CP_ASYNC_COMMIT() asm volatile("cp.async.commit_group;\n" ::: "memory")
#define CP_ASYNC_WAIT0()  asm volatile("cp.async.wait_group 0;\n" ::: "memory")

// ============================================================================
// Big FP16 NT GEMM: 128x128 block, 4 warps (2x2), 64x64 warp tile, BK=64 halfs,
// cp.async double buffer. C[m][n] = sum_k A[m][k]*Bm[n][k], fp32 accumulate.
// Epilogue modes:
//   Fout != 0 : Fout[m][n] = acc + Cadd[m][n]                (GEMM2)
//   else      : gc < split -> Pout[m][gc] = acc + bias[gc]   (fp32, P path)
//               gc >= split-> Hout[m][gc-split] = half(gelu(acc + bias[gc]))
// ============================================================================
template <int BM, int BN, int BK>
__launch_bounds__(128, 2)
__global__ void gemm_f16_nt(const __half* __restrict__ A, int lda,
                            const __half* __restrict__ Bm, int ldb,
                            int K,
                            const float* __restrict__ bias,
                            float* __restrict__ Pout, __half* __restrict__ Hout, int split,
                            float* __restrict__ Fout, const float* __restrict__ Cadd,
                            int ldo) {
    constexpr int BKP = BK + 8;       // pitch in halfs: 72 -> 144 B, conflict-free
    constexpr int WM = 64, WN = 64;
    constexpr int MT = WM / 16;       // 4
    constexpr int NT = WN / 8;        // 8

    extern __shared__ __half smh[];
    __half* sA = smh;                         // [2][BM*BKP]
    __half* sB = smh + 2 * BM * BKP;          // [2][BN*BKP]

    const int tid  = threadIdx.x;
    const int warp = tid >> 5, lane = tid & 31;
    const int wm = warp >> 1, wn = warp & 1;
    const int r4 = lane >> 2, c4 = lane & 3;
    const int bm = blockIdx.y * BM;
    const int bn = blockIdx.x * BN;

    const __half* Ab = A  + (size_t)bm * lda;
    const __half* Bb = Bm + (size_t)bn * ldb;

    float acc[MT][NT][4];
#pragma unroll
    for (int mt = 0; mt < MT; mt++)
#pragma unroll
        for (int nt = 0; nt < NT; nt++)
#pragma unroll
            for (int i = 0; i < 4; i++) acc[mt][nt][i] = 0.0f;

    auto load_stage = [&](int kt, int st) {
        __half* dA = sA + st * BM * BKP;
        __half* dB = sB + st * BN * BKP;
#pragma unroll
        for (int i = 0; i < (BM * BK / 8) / 128; i++) {
            int e = tid + i * 128;
            int row = e / (BK / 8);
            int col = (e % (BK / 8)) * 8;
            cp_async16(dA + row * BKP + col, Ab + (size_t)row * lda + kt + col);
        }
#pragma unroll
        for (int i = 0; i < (BN * BK / 8) / 128; i++) {
            int e = tid + i * 128;
            int row = e / (BK / 8);
            int col = (e % (BK / 8)) * 8;
            cp_async16(dB + row * BKP + col, Bb + (size_t)row * ldb + kt + col);
        }
    };

    load_stage(0, 0);
    CP_ASYNC_COMMIT();
    CP_ASYNC_WAIT0();
    __syncthreads();

    int buf = 0;
    for (int kt = 0; kt < K; kt += BK) {
        const bool has_next = (kt + BK) < K;
        if (has_next) {
            load_stage(kt + BK, buf ^ 1);
            CP_ASYNC_COMMIT();
        }

        const __half* cA = sA + buf * BM * BKP;
        const __half* cB = sB + buf * BN * BKP;
#pragma unroll
        for (int ks = 0; ks < BK; ks += 16) {
            uint32_t af[MT][4];
            uint32_t bf[NT][2];
#pragma unroll
            for (int mt = 0; mt < MT; mt++) {
                const __half* p = cA + (wm * WM + mt * 16 + r4) * BKP + ks + 2 * c4;
                af[mt][0] = *reinterpret_cast<const uint32_t*>(p);
                af[mt][1] = *reinterpret_cast<const uint32_t*>(p + 8 * BKP);
                af[mt][2] = *reinterpret_cast<const uint32_t*>(p + 8);
                af[mt][3] = *reinterpret_cast<const uint32_t*>(p + 8 * BKP + 8);
            }
#pragma unroll
            for (int nt = 0; nt < NT; nt++) {
                const __half* p = cB + (wn * WN + nt * 8 + r4) * BKP + ks + 2 * c4;
                bf[nt][0] = *reinterpret_cast<const uint32_t*>(p);
                bf[nt][1] = *reinterpret_cast<const uint32_t*>(p + 8);
            }
#pragma unroll
            for (int mt = 0; mt < MT; mt++)
#pragma unroll
                for (int nt = 0; nt < NT; nt++)
                    mma_f16_16n8k16(acc[mt][nt], af[mt], bf[nt]);
        }

        if (has_next) CP_ASYNC_WAIT0();
        __syncthreads();
        buf ^= 1;
    }

    // --- epilogue ---
#pragma unroll
    for (int mt = 0; mt < MT; mt++) {
        int gr = bm + wm * WM + mt * 16 + r4;
#pragma unroll
        for (int nt = 0; nt < NT; nt++) {
            int gc = bn + wn * WN + nt * 8 + c4 * 2;
            float2 v0 = make_float2(acc[mt][nt][0], acc[mt][nt][1]);
            float2 v1 = make_float2(acc[mt][nt][2], acc[mt][nt][3]);
            if (Fout) {
                v0.x += Cadd[(size_t)gr * ldo + gc];
                v0.y += Cadd[(size_t)gr * ldo + gc + 1];
                v1.x += Cadd[(size_t)(gr + 8) * ldo + gc];
                v1.y += Cadd[(size_t)(gr + 8) * ldo + gc + 1];
                *reinterpret_cast<float2*>(Fout + (size_t)gr * ldo + gc) = v0;
                *reinterpret_cast<float2*>(Fout + (size_t)(gr + 8) * ldo + gc) = v1;
            } else {
                float bx = bias[gc], by = bias[gc + 1];
                v0.x += bx; v0.y += by; v1.x += bx; v1.y += by;
                if (gc < split) {
                    *reinterpret_cast<float2*>(Pout + (size_t)gr * ldo + gc) = v0;
                    *reinterpret_cast<float2*>(Pout + (size_t)(gr + 8) * ldo + gc) = v1;
                } else {
                    int hc = gc - split;
                    __half2 h0 = __floats2half2_rn(gelu_exact(v0.x), gelu_exact(v0.y));
                    __half2 h1 = __floats2half2_rn(gelu_exact(v1.x), gelu_exact(v1.y));
                    *reinterpret_cast<__half2*>(Hout + (size_t)gr * ldo + hc) = h0;
                    *reinterpret_cast<__half2*>(Hout + (size_t)(gr + 8) * ldo + hc) = h1;
                }
            }
        }
    }
}

// ============================================================================
// Pipelined TF32 NN GEMM for weight precompute (fp32 in/out).
// C = A[M,K] @ Bm[K,N]. 128x128x32, 256 threads (2x4 warps, 64x32 tiles).
// ============================================================================
template <int BM, int BN, int BK>
__launch_bounds__(256)
__global__ void gemm_tf32_nn_pipe(const float* __restrict__ A, int lda,
                                  const float* __restrict__ Bm, int ldb,
                                  float* __restrict__ C, int ldc, int K) {
    constexpr int BKP = BK + 4;
    constexpr int BNP = BN + 4;
    constexpr int WM = BM / 2;
    constexpr int WN = BN / 4;
    constexpr int MT = WM / 16;
    constexpr int NT = WN / 8;

    extern __shared__ float smem[];
    float* sA = smem;                      // [2][BM*BKP]
    float* sB = smem + 2 * BM * BKP;       // [2][BK*BNP]  (k-major)

    const int tid  = threadIdx.x;
    const int warp = tid >> 5, lane = tid & 31;
    const int wm = warp >> 2, wn = warp & 3;
    const int r4 = lane >> 2, c4 = lane & 3;
    const int bm = blockIdx.y * BM;
    const int bn = blockIdx.x * BN;

    const float* Ab = A + (size_t)bm * lda;

    float acc[MT][NT][4];
#pragma unroll
    for (int mt = 0; mt < MT; mt++)
#pragma unroll
        for (int nt = 0; nt < NT; nt++)
#pragma unroll
            for (int i = 0; i < 4; i++) acc[mt][nt][i] = 0.0f;

    auto load_stage = [&](int kt, int st) {
        float* dA = sA + st * BM * BKP;
        float* dB = sB + st * BK * BNP;
#pragma unroll
        for (int i = 0; i < (BM * BK / 4) / 256; i++) {
            int e = tid + i * 256;
            int row = e / (BK / 4);
            int col = (e % (BK / 4)) * 4;
            cp_async16(dA + row * BKP + col, Ab + (size_t)row * lda + kt + col);
        }
#pragma unroll
        for (int i = 0; i < (BK * BN / 4) / 256; i++) {
            int e = tid + i * 256;
            int row = e / (BN / 4);
            int col = (e % (BN / 4)) * 4;
            cp_async16(dB + row * BNP + col, Bm + (size_t)(kt + row) * ldb + bn + col);
        }
    };

    load_stage(0, 0);
    CP_ASYNC_COMMIT();
    CP_ASYNC_WAIT0();
    __syncthreads();

    int buf = 0;
    for (int kt = 0; kt < K; kt += BK) {
        const bool has_next = (kt + BK) < K;
        if (has_next) {
            load_stage(kt + BK, buf ^ 1);
            CP_ASYNC_COMMIT();
        }

        const float* cA = sA + buf * BM * BKP;
        const float* cB = sB + buf * BK * BNP;
#pragma unroll
        for (int ks = 0; ks < BK; ks += 8) {
            uint32_t af[MT][4];
            uint32_t bf[NT][2];
#pragma unroll
            for (int mt = 0; mt < MT; mt++) {
                const float* p = cA + (wm * WM + mt * 16 + r4) * BKP + ks + c4;
                af[mt][0] = __float_as_uint(p[0]);
                af[mt][1] = __float_as_uint(p[8 * BKP]);
                af[mt][2] = __float_as_uint(p[4]);
                af[mt][3] = __float_as_uint(p[8 * BKP + 4]);
            }
#pragma unroll
            for (int nt = 0; nt < NT; nt++) {
                const float* p = cB + (size_t)(ks + c4) * BNP + wn * WN + nt * 8 + r4;
                bf[nt][0] = __float_as_uint(p[0]);
                bf[nt][1] = __float_as_uint(p[4 * BNP]);
            }
#pragma unroll
            for (int mt = 0; mt < MT; mt++)
#pragma unroll
                for (int nt = 0; nt < NT; nt++)
                    mma_tf32_16n8k8(acc[mt][nt], af[mt], bf[nt]);
        }

        if (has_next) CP_ASYNC_WAIT0();
        __syncthreads();
        buf ^= 1;
    }

#pragma unroll
    for (int mt = 0; mt < MT; mt++) {
        int gr = bm + wm * WM + mt * 16 + r4;
#pragma unroll
        for (int nt = 0; nt < NT; nt++) {
            int gc = bn + wn * WN + nt * 8 + c4 * 2;
            float2 v0 = make_float2(acc[mt][nt][0], acc[mt][nt][1]);
            float2 v1 = make_float2(acc[mt][nt][2], acc[mt][nt][3]);
            *reinterpret_cast<float2*>(C + (size_t)gr * ldc + gc) = v0;
            *reinterpret_cast<float2*>(C + (size_t)(gr + 8) * ldc + gc) = v1;
        }
    }
}

// ---------------- pack / convert kernels ----------------
// X fp16 = [gnn | tr]
__global__ void pack_Xh_kernel(const float* __restrict__ gnn, const float* __restrict__ tr,
                               __half* __restrict__ X) {
    const int R4 = 1280 / 4;  // 320
    size_t i = (size_t)blockIdx.x * blockDim.x + threadIdx.x;
    if (i >= (size_t)B_ROWS * R4) return;
    int row = (int)(i / R4);
    int c4  = (int)(i % R4);
    float4 v;
    if (c4 < GNN_D / 4)
        v = reinterpret_cast<const float4*>(gnn)[(size_t)row * (GNN_D / 4) + c4];
    else
        v = reinterpret_cast<const float4*>(tr)[(size_t)row * (TR_D / 4) + (c4 - GNN_D / 4)];
    __half2* dst = reinterpret_cast<__half2*>(X) + (size_t)row * (1280 / 2) + c4 * 2;
    dst[0] = __floats2half2_rn(v.x, v.y);
    dst[1] = __floats2half2_rn(v.z, v.w);
}

// Wcat rows 0..1023 (fp32) = [Wg | Wt]
__global__ void pack_W_kernel(const float* __restrict__ Wg, const float* __restrict__ Wt,
                              float* __restrict__ Wcat) {
    const int R4 = 1280 / 4;
    size_t i = (size_t)blockIdx.x * blockDim.x + threadIdx.x;
    if (i >= (size_t)F_D * R4) return;
    int row = (int)(i / R4);
    int c4  = (int)(i % R4);
    float4 v;
    if (c4 < GNN_D / 4)
        v = reinterpret_cast<const float4*>(Wg)[(size_t)row * (GNN_D / 4) + c4];
    else
        v = reinterpret_cast<const float4*>(Wt)[(size_t)row * (TR_D / 4) + (c4 - GNN_D / 4)];
    reinterpret_cast<float4*>(Wcat)[i] = v;
}

// W1s = [W1[:, :1024] ; W1[:, 1024:]]  (2048x1024)
__global__ void pack_W1s_kernel(const float* __restrict__ W1, float* __restrict__ W1s) {
    const int R4 = F_D / 4;  // 256
    size_t i = (size_t)blockIdx.x * blockDim.x + threadIdx.x;
    if (i >= (size_t)2 * F_D * R4) return;
    int row = (int)(i / R4);
    int c4  = (int)(i % R4);
    int srow = row & (F_D - 1);
    int half = row >> 10;
    float4 v = reinterpret_cast<const float4*>(W1)[(size_t)srow * (2 * F_D / 4) + half * R4 + c4];
    reinterpret_cast<float4*>(W1s)[i] = v;
}

// generic fp32 -> fp16 convert (n4 = element count / 4)
__global__ void f2h_kernel(const float* __restrict__ src, __half* __restrict__ dst, size_t n4) {
    size_t i = (size_t)blockIdx.x * blockDim.x + threadIdx.x;
    if (i >= n4) return;
    float4 v = reinterpret_cast<const float4*>(src)[i];
    __half2* d = reinterpret_cast<__half2*>(dst) + i * 2;
    d[0] = __floats2half2_rn(v.x, v.y);
    d[1] = __floats2half2_rn(v.z, v.w);
}

// ---------------- bias kernels (tiny, fp32) ----------------
__global__ void bias_c_kernel(const float* __restrict__ Wo, const float* __restrict__ bv,
                              const float* __restrict__ bo, float* __restrict__ cvec) {
    int i = blockIdx.x * blockDim.x + threadIdx.x;
    if (i >= F_D) return;
    float s = bo[i];
    const float* r = Wo + (size_t)i * F_D;
    for (int k = 0; k < F_D; k++) s += r[k] * bv[k];
    cvec[i] = s;
}

// bias1[0:1024]    = bg + bt + b2
// bias1[1024:2048] = b1 + T1@bt + T2@bg + (W1a + W1b)@cvec
__global__ void bias_rest_kernel(const float* __restrict__ Tcat,
                                 const float* __restrict__ W1, const float* __restrict__ b1,
                                 const float* __restrict__ bg, const float* __restrict__ bt,
                                 const float* __restrict__ b2, const float* __restrict__ cvec,
                                 float* __restrict__ bias1) {
    int i = blockIdx.x * blockDim.x + threadIdx.x;
    if (i >= F_D) return;
    float s = b1[i];
    const float* r1 = Tcat + (size_t)i * F_D;
    const float* r2 = Tcat + (size_t)(F_D + i) * F_D;
    const float* w1 = W1 + (size_t)i * (2 * F_D);
    for (int k = 0; k < F_D; k++) {
        s += r1[k] * bt[k];
        s += r2[k] * bg[k];
        s += (w1[k] + w1[F_D + k]) * cvec[k];
    }
    bias1[F_D + i] = s;
    bias1[i] = bg[i] + bt[i] + b2[i];
}

// ---------------- host-side launch helpers ----------------
static void run_gemm_f16_nt(const __half* A, int lda, const __half* Bm, int ldb,
                            int M, int N, int K,
                            const float* bias, float* Pout, __half* Hout, int split,
                            float* Fout, const float* Cadd, int ldo) {
    constexpr int BM = 128, BN = 128, BK = 64;
    constexpr int SMEM = 2 * (BM + BN) * (BK + 8) * (int)sizeof(__half);  // 73728 B
    static bool attr_done = false;
    if (!attr_done) {
        cudaFuncSetAttribute(gemm_f16_nt<BM, BN, BK>,
                             cudaFuncAttributeMaxDynamicSharedMemorySize, SMEM);
        attr_done = true;
    }
    dim3 grid(N / BN, M / BM);
    gemm_f16_nt<BM, BN, BK><<<grid, 128, SMEM>>>(A, lda, Bm, ldb, K, bias,
                                                 Pout, Hout, split, Fout, Cadd, ldo);
}

static void run_gemm_nn(const float* A, int lda, const float* Bm, int ldb,
                        float* C, int ldc, int M, int N, int K) {
    constexpr int BM = 128, BN = 128, BK = 32;
    constexpr int SMEM = (2 * BM * (BK + 4) + 2 * BK * (BN + 4)) * (int)sizeof(float);
    static bool attr_done = false;
    if (!attr_done) {
        cudaFuncSetAttribute(gemm_tf32_nn_pipe<BM, BN, BK>,
                             cudaFuncAttributeMaxDynamicSharedMemorySize, SMEM);
        attr_done = true;
    }
    dim3 grid(N / BN, M / BM);
    gemm_tf32_nn_pipe<BM, BN, BK><<<grid, 256, SMEM>>>(A, lda, Bm, ldb, C, ldc, K);
}

extern "C" void kernel_launch(void* const* d_in, const int* in_sizes, int n_in,
                              void* d_out, int out_size) {
    const float* gnn = (const float*)d_in[0];
    const float* tr  = (const float*)d_in[1];
    const float* Wg  = (const float*)d_in[2];
    const float* bg  = (const float*)d_in[3];
    const float* Wt  = (const float*)d_in[4];
    const float* bt  = (const float*)d_in[5];
    const float* Wv  = (const float*)d_in[6];
    const float* bv  = (const float*)d_in[7];
    const float* Wo  = (const float*)d_in[8];
    const float* bo  = (const float*)d_in[9];
    const float* W1  = (const float*)d_in[10];
    const float* b1  = (const float*)d_in[11];
    const float* W2  = (const float*)d_in[12];
    const float* b2  = (const float*)d_in[13];
    float* out = (float*)d_out;

    __half *Xh, *H, *Wh, *W2h;
    float *P, *Wcat, *Mm, *W1s, *Tcat, *cvec, *bias1;
    cudaGetSymbolAddress((void**)&Xh,    g_Xh);
    cudaGetSymbolAddress((void**)&H,     g_H);
    cudaGetSymbolAddress((void**)&P,     g_P);
    cudaGetSymbolAddress((void**)&Wcat,  g_Wcat);
    cudaGetSymbolAddress((void**)&Wh,    g_Wh);
    cudaGetSymbolAddress((void**)&W2h,   g_W2h);
    cudaGetSymbolAddress((void**)&Mm,    g_Mm);
    cudaGetSymbolAddress((void**)&W1s,   g_W1s);
    cudaGetSymbolAddress((void**)&Tcat,  g_Tcat);
    cudaGetSymbolAddress((void**)&cvec,  g_cvec);
    cudaGetSymbolAddress((void**)&bias1, g_bias1);

    // Packs
    {
        size_t n4 = (size_t)B_ROWS * (1280 / 4);
        pack_Xh_kernel<<<(unsigned)((n4 + 255) / 256), 256>>>(gnn, tr, Xh);
        size_t w4 = (size_t)F_D * (1280 / 4);
        pack_W_kernel<<<(unsigned)((w4 + 255) / 256), 256>>>(Wg, Wt, Wcat);
        size_t s4 = (size_t)2 * F_D * (F_D / 4);
        pack_W1s_kernel<<<(unsigned)((s4 + 255) / 256), 256>>>(W1, W1s);
        size_t r4 = (size_t)F_D * F_D / 4;
        f2h_kernel<<<(unsigned)((r4 + 255) / 256), 256>>>(W2, W2h, r4);
    }

    // Weight-space precompute (tf32, fp32 out):
    // Mm = Wo@Wv;  [T1;T2] = W1s@Mm;  Wcat[1024:2048] = [T2@Wg | T1@Wt]
    run_gemm_nn(Wo, F_D, Wv, F_D, Mm, F_D, F_D, F_D, F_D);
    run_gemm_nn(W1s, F_D, Mm, F_D, Tcat, F_D, 2 * F_D, F_D, F_D);
    run_gemm_nn(Tcat + (size_t)F_D * F_D, F_D, Wg, GNN_D,
                Wcat + (size_t)F_D * 1280, 1280, F_D, GNN_D, F_D);           // Cg = T2@Wg
    run_gemm_nn(Tcat, F_D, Wt, TR_D,
                Wcat + (size_t)F_D * 1280 + GNN_D, 1280, F_D, TR_D, F_D);    // Ct = T1@Wt

    // Convert full Wcat (2048x1280) to fp16
    {
        size_t c4 = (size_t)2048 * 1280 / 4;
        f2h_kernel<<<(unsigned)((c4 + 255) / 256), 256>>>(Wcat, Wh, c4);
    }

    // Bias vectors
    bias_c_kernel<<<8, 128>>>(Wo, bv, bo, cvec);
    bias_rest_kernel<<<8, 128>>>(Tcat, W1, b1, bg, bt, b2, cvec, bias1);

    // GEMM1 (fp16): cols 0..1023  -> P   = X@[Wg|Wt].T + (bg+bt+b2)   (fp32)
    //               cols 1024..   -> H   = half(gelu(X@[Cg|Ct].T + bh))
    run_gemm_f16_nt(Xh, 1280, Wh, 1280, B_ROWS, 2048, 1280,
                    bias1, P, H, 1024, nullptr, nullptr, 1024);

    // GEMM2 (fp16): out = H @ W2.T + P
    run_gemm_f16_nt(H, 1024, W2h, 1024, B_ROWS, 1024, 1024,
                    nullptr, nullptr, nullptr, 0, out, P, 1024);
}